// round 1
// baseline (speedup 1.0000x reference)
#include <cuda_runtime.h>
#include <math.h>

#define N_STATES   25
#define LUT_PITCH  64   // padded row pitch (>= max obs value 50), multiple of 32 banks
#define LUT_SIZE   (N_STATES * LUT_PITCH)

// Scratch LUT (allocation-free rule: __device__ global).
__device__ float g_lut[LUT_SIZE];

// Build the 25x50 log-prob table. Row 0 = bookend; rows 1..24 = NB log-pmf.
// Done in double precision — cost is negligible (1600 threads).
__global__ void build_lut_kernel(const float* __restrict__ means,
                                 const float* __restrict__ phis) {
    int idx = blockIdx.x * blockDim.x + threadIdx.x;
    if (idx >= LUT_SIZE) return;
    int s = idx / LUT_PITCH;
    int x = idx % LUT_PITCH;
    float v;
    if (s == 0) {
        v = (x > 0) ? -100000.0f : 0.0f;
    } else {
        double mu  = (double)means[s];
        double phi = (double)phis[s];
        double xd  = (double)x;
        double nb = lgamma(xd + phi) - lgamma(phi) - lgamma(xd + 1.0)
                  + phi * log(phi / (phi + mu))
                  + xd  * log(mu  / (phi + mu));
        v = (float)nb;
    }
    g_lut[idx] = v;
}

// Main kernel: out[s][i] = LUT[s][obs[i]] for s in 0..24.
// Each thread handles 4 consecutive spots (int4 load, float4 stores).
__global__ void __launch_bounds__(256) emit_kernel(const int* __restrict__ obs,
                                                   float* __restrict__ out,
                                                   int n_groups,       // n_spots/4
                                                   long long n_spots) {
    __shared__ float lut[LUT_SIZE];
    for (int i = threadIdx.x; i < LUT_SIZE; i += blockDim.x)
        lut[i] = g_lut[i];
    __syncthreads();

    const int4* obs4 = (const int4*)obs;
    long long stride = (long long)gridDim.x * blockDim.x;
    for (long long g = (long long)blockIdx.x * blockDim.x + threadIdx.x;
         g < n_groups; g += stride) {
        int4 o = obs4[g];
        #pragma unroll
        for (int s = 0; s < N_STATES; s++) {
            const float* row = lut + s * LUT_PITCH;
            float4 v;
            v.x = row[o.x];
            v.y = row[o.y];
            v.z = row[o.z];
            v.w = row[o.w];
            ((float4*)(out + (long long)s * n_spots))[g] = v;
        }
    }
}

// Scalar tail for n_spots not divisible by 4 (not hit for N_SPOTS=4M, safety).
__global__ void emit_tail_kernel(const int* __restrict__ obs,
                                 float* __restrict__ out,
                                 int tail_start, int n_spots_i,
                                 long long n_spots) {
    int i = tail_start + blockIdx.x * blockDim.x + threadIdx.x;
    if (i >= n_spots_i) return;
    int x = obs[i];
    #pragma unroll
    for (int s = 0; s < N_STATES; s++)
        out[(long long)s * n_spots + i] = g_lut[s * LUT_PITCH + x];
}

extern "C" void kernel_launch(void* const* d_in, const int* in_sizes, int n_in,
                              void* d_out, int out_size) {
    const float* state_means = (const float*)d_in[0];
    const float* state_phis  = (const float*)d_in[1];
    const int*   obs         = (const int*)d_in[2];
    float*       out         = (float*)d_out;

    int n_spots_i = in_sizes[2];
    long long n_spots = (long long)n_spots_i;

    build_lut_kernel<<<(LUT_SIZE + 255) / 256, 256>>>(state_means, state_phis);

    int n_groups = n_spots_i / 4;
    if (n_groups > 0) {
        int blocks = 148 * 8;  // grid-stride; amortize smem LUT fill
        long long total_threads = (long long)blocks * 256;
        if (total_threads > n_groups)
            blocks = (n_groups + 255) / 256;
        emit_kernel<<<blocks, 256>>>(obs, out, n_groups, n_spots);
    }

    int tail_start = n_groups * 4;
    int tail = n_spots_i - tail_start;
    if (tail > 0) {
        emit_tail_kernel<<<(tail + 255) / 256, 256>>>(obs, out, tail_start,
                                                      n_spots_i, n_spots);
    }
}

// round 2
// speedup vs baseline: 1.4495x; 1.4495x over previous
#include <cuda_runtime.h>
#include <math.h>

#define N_STATES   25
#define LUT_PITCH  64   // padded row pitch (>= max obs value 50), multiple of 32 banks
#define LUT_SIZE   (N_STATES * LUT_PITCH)

// Scratch LUT (allocation-free rule: __device__ global).
__device__ float g_lut[LUT_SIZE];

// Build the 25x64 log-prob table in fp32. Row 0 = bookend; rows 1..24 = NB log-pmf.
// fp32 lgammaf is ~2 orders of magnitude cheaper than f64 lgamma here, and the
// cancellation error bound (~2.5e-4 abs on O(10) values) is far below the 1e-3 gate.
__global__ void build_lut_kernel(const float* __restrict__ means,
                                 const float* __restrict__ phis) {
    int idx = blockIdx.x * blockDim.x + threadIdx.x;
    if (idx >= LUT_SIZE) return;
    int s = idx / LUT_PITCH;
    int x = idx % LUT_PITCH;
    float v;
    if (s == 0) {
        v = (x > 0) ? -100000.0f : 0.0f;
    } else {
        float mu  = means[s];
        float phi = phis[s];
        float xf  = (float)x;
        float inv = 1.0f / (phi + mu);
        float nb = lgammaf(xf + phi) - lgammaf(phi) - lgammaf(xf + 1.0f)
                 + phi * logf(phi * inv)
                 + xf  * logf(mu  * inv);
        v = nb;
    }
    g_lut[idx] = v;
}

// Main kernel: out[s][i] = LUT[s][obs[i]] for s in 0..24.
// Each thread handles 4 consecutive spots (int4 load, float4 streaming stores).
__global__ void __launch_bounds__(256) emit_kernel(const int* __restrict__ obs,
                                                   float* __restrict__ out,
                                                   int n_groups,       // n_spots/4
                                                   long long n_spots) {
    __shared__ float lut[LUT_SIZE];
    for (int i = threadIdx.x; i < LUT_SIZE; i += blockDim.x)
        lut[i] = g_lut[i];
    __syncthreads();

    const int4* obs4 = (const int4*)obs;
    long long stride = (long long)gridDim.x * blockDim.x;
    for (long long g = (long long)blockIdx.x * blockDim.x + threadIdx.x;
         g < n_groups; g += stride) {
        int4 o = obs4[g];
        #pragma unroll
        for (int s = 0; s < N_STATES; s++) {
            const float* row = lut + s * LUT_PITCH;
            float4 v;
            v.x = row[o.x];
            v.y = row[o.y];
            v.z = row[o.z];
            v.w = row[o.w];
            // Output is write-once, never re-read: streaming (evict-first) store.
            __stcs((float4*)(out + (long long)s * n_spots) + g, v);
        }
    }
}

// Scalar tail for n_spots not divisible by 4 (not hit for N_SPOTS=4M, safety).
__global__ void emit_tail_kernel(const int* __restrict__ obs,
                                 float* __restrict__ out,
                                 int tail_start, int n_spots_i,
                                 long long n_spots) {
    int i = tail_start + blockIdx.x * blockDim.x + threadIdx.x;
    if (i >= n_spots_i) return;
    int x = obs[i];
    #pragma unroll
    for (int s = 0; s < N_STATES; s++)
        out[(long long)s * n_spots + i] = g_lut[s * LUT_PITCH + x];
}

extern "C" void kernel_launch(void* const* d_in, const int* in_sizes, int n_in,
                              void* d_out, int out_size) {
    const float* state_means = (const float*)d_in[0];
    const float* state_phis  = (const float*)d_in[1];
    const int*   obs         = (const int*)d_in[2];
    float*       out         = (float*)d_out;

    int n_spots_i = in_sizes[2];
    long long n_spots = (long long)n_spots_i;

    build_lut_kernel<<<(LUT_SIZE + 255) / 256, 256>>>(state_means, state_phis);

    int n_groups = n_spots_i / 4;
    if (n_groups > 0) {
        int blocks = 148 * 8;  // one full wave at 256 threads/block
        long long total_threads = (long long)blocks * 256;
        if (total_threads > n_groups)
            blocks = (int)((n_groups + 255) / 256);
        emit_kernel<<<blocks, 256>>>(obs, out, n_groups, n_spots);
    }

    int tail_start = n_groups * 4;
    int tail = n_spots_i - tail_start;
    if (tail > 0) {
        emit_tail_kernel<<<(tail + 255) / 256, 256>>>(obs, out, tail_start,
                                                      n_spots_i, n_spots);
    }
}